// round 7
// baseline (speedup 1.0000x reference)
#include <cuda_runtime.h>
#include <cuda_bf16.h>
#include <mma.h>
#include <math.h>
#include <stdint.h>

using namespace nvcuda;

// Problem constants (fixed shapes)
#define NB      128          // batch
#define SS      128          // seq
#define EE      1024         // embed
#define NQ      8            // qubits
#define NL      4            // layers
#define DIMQ    256          // 2^NQ
#define ROWS    16384        // NB*SS
#define KSPLIT  3072         // 3*EE (bf16 split-concat K)
#define KAV     384          // 3*SS  (attn@V split K)
#define Y_SIZE  16777216L    // NB*SS*EE

// Scratch (static device globals — allowed)
__device__ float  d_qin[ROWS * NQ];
__device__ float2 d_gates[NL * NQ * 4];
__device__ int    d_perm[DIMQ];
__device__ float2 d_psi[(long)ROWS * DIMQ];
__device__ float  d_V[(long)ROWS * EE];
__device__ float  d_T[(long)ROWS * EE];
__device__ __nv_bfloat16 d_Xs[(long)ROWS * KSPLIT];    // split X    [M][3K]
__device__ __nv_bfloat16 d_Ts[(long)ROWS * KSPLIT];    // split T    [M][3K]
__device__ __nv_bfloat16 d_Wvs[(long)EE * KSPLIT];     // split Wv^T [N][3K]
__device__ __nv_bfloat16 d_Wos[(long)EE * KSPLIT];     // split Wo^T [N][3K]
__device__ __nv_bfloat16 d_attns[(long)ROWS * KAV];    // split attn [b*s][3*128]
__device__ __nv_bfloat16 d_Vts[(long)NB * EE * KAV];   // split V^T  [b][e][3*128]

#define FULLM 0xffffffffu

// ---------------------------------------------------------------------------
// cp.async helpers (sm_80+ baseline — no 'a'-suffix features!)
// ---------------------------------------------------------------------------
__device__ __forceinline__ uint32_t smem_u32(const void* p) {
    uint32_t a;
    asm("{ .reg .u64 t; cvta.to.shared.u64 t, %1; cvt.u32.u64 %0, t; }" : "=r"(a) : "l"(p));
    return a;
}
__device__ __forceinline__ void cp16(uint32_t s, const void* g) {
    asm volatile("cp.async.cg.shared.global [%0], [%1], 16;" :: "r"(s), "l"(g));
}
#define CP_COMMIT() asm volatile("cp.async.commit_group;" ::: "memory")
#define CP_WAIT1()  asm volatile("cp.async.wait_group 1;" ::: "memory")
#define CP_WAIT0()  asm volatile("cp.async.wait_group 0;" ::: "memory")

// ---------------------------------------------------------------------------
// Prep: fused RZ*RY gate matrices, composed CNOT-ring perm
// ---------------------------------------------------------------------------
__global__ void prep_kernel(const float* __restrict__ theta) {
    int t = threadIdx.x;
    if (t < NL * NQ) {
        float ty = theta[t * 2 + 0];
        float tz = theta[t * 2 + 1];
        float s, c, zs, zc;
        sincosf(0.5f * ty, &s, &c);
        sincosf(0.5f * tz, &zs, &zc);
        d_gates[t * 4 + 0] = make_float2( c * zc, -c * zs);
        d_gates[t * 4 + 1] = make_float2(-s * zc,  s * zs);
        d_gates[t * 4 + 2] = make_float2( s * zc,  s * zs);
        d_gates[t * 4 + 3] = make_float2( c * zc,  c * zs);
    }
    if (t < DIMQ) {
        int j = t;
        #pragma unroll
        for (int q = NQ - 1; q >= 0; q--) {
            int tq   = (q + 1) & (NQ - 1);
            int cpos = NQ - 1 - q;
            int tpos = NQ - 1 - tq;
            if ((j >> cpos) & 1) j ^= (1 << tpos);
        }
        d_perm[t] = j;
    }
}

// ---------------------------------------------------------------------------
// splitA: fp32 [R x 1024] -> bf16 [R x 3072] laid out [hi | lo | hi]
// ---------------------------------------------------------------------------
__global__ __launch_bounds__(256) void splitA_kernel(const float* __restrict__ src,
                                                     __nv_bfloat16* __restrict__ dst) {
    long i = (long)blockIdx.x * 256 + threadIdx.x;   // float4 index
    float4 v = ((const float4*)src)[i];
    long r  = i >> 8;
    int  c4 = (int)(i & 255) * 4;
    float vv[4] = {v.x, v.y, v.z, v.w};
    union { __nv_bfloat16 b[4]; uint2 u; } H, L;
    #pragma unroll
    for (int j = 0; j < 4; j++) {
        __nv_bfloat16 h = __float2bfloat16(vv[j]);
        H.b[j] = h;
        L.b[j] = __float2bfloat16(vv[j] - __bfloat162float(h));
    }
    __nv_bfloat16* row = dst + r * KSPLIT;
    *(uint2*)(row + c4)        = H.u;
    *(uint2*)(row + EE + c4)   = L.u;
    *(uint2*)(row + 2*EE + c4) = H.u;
}

// ---------------------------------------------------------------------------
// splitAttn: attn fp32 [16384 x 128] -> bf16 [16384 x 384] = [hi | lo | hi]
// ---------------------------------------------------------------------------
__global__ __launch_bounds__(256) void splitAttn_kernel(const float* __restrict__ src,
                                                        __nv_bfloat16* __restrict__ dst) {
    long i = (long)blockIdx.x * 256 + threadIdx.x;   // float4 index (16384*32 total)
    float4 v = ((const float4*)src)[i];
    long r  = i >> 5;
    int  c4 = (int)(i & 31) * 4;
    float vv[4] = {v.x, v.y, v.z, v.w};
    union { __nv_bfloat16 b[4]; uint2 u; } H, L;
    #pragma unroll
    for (int j = 0; j < 4; j++) {
        __nv_bfloat16 h = __float2bfloat16(vv[j]);
        H.b[j] = h;
        L.b[j] = __float2bfloat16(vv[j] - __bfloat162float(h));
    }
    __nv_bfloat16* row = dst + r * KAV;
    *(uint2*)(row + c4)          = H.u;
    *(uint2*)(row + SS + c4)     = L.u;
    *(uint2*)(row + 2*SS + c4)   = H.u;
}

// ---------------------------------------------------------------------------
// splitB: W fp32 [K=1024][N=1024] -> Bt bf16 [N][3072] = [hi | hi | lo] transposed
// ---------------------------------------------------------------------------
__global__ __launch_bounds__(256) void splitB_kernel(const float* __restrict__ W,
                                                     __nv_bfloat16* __restrict__ Bt) {
    __shared__ float tile[32][33];
    int k0 = blockIdx.y * 32, n0 = blockIdx.x * 32;
    int tx = threadIdx.x & 31, ty = threadIdx.x >> 5;  // 32 x 8
    #pragma unroll
    for (int j = 0; j < 32; j += 8)
        tile[ty + j][tx] = W[(long)(k0 + ty + j) * EE + n0 + tx];
    __syncthreads();
    #pragma unroll
    for (int j = 0; j < 32; j += 8) {
        int n = n0 + ty + j, k = k0 + tx;
        float v = tile[tx][ty + j];
        __nv_bfloat16 h = __float2bfloat16(v);
        __nv_bfloat16 l = __float2bfloat16(v - __bfloat162float(h));
        __nv_bfloat16* row = Bt + (long)n * KSPLIT;
        row[k]          = h;
        row[EE + k]     = h;
        row[2*EE + k]   = l;
    }
}

// ---------------------------------------------------------------------------
// splitVt: V fp32 [b*128+t][e] -> Vts bf16 [b][e][384] = [hi(t) | hi(t) | lo(t)]
// ---------------------------------------------------------------------------
__global__ __launch_bounds__(256) void splitVt_kernel(const float* __restrict__ V,
                                                      __nv_bfloat16* __restrict__ Vts) {
    __shared__ float tile[32][33];
    int b  = blockIdx.z;
    int t0 = blockIdx.y * 32, e0 = blockIdx.x * 32;
    int tx = threadIdx.x & 31, ty = threadIdx.x >> 5;  // 32 x 8
    #pragma unroll
    for (int j = 0; j < 32; j += 8)
        tile[ty + j][tx] = V[((long)b * SS + t0 + ty + j) * EE + e0 + tx];  // tile[t][e]
    __syncthreads();
    #pragma unroll
    for (int j = 0; j < 32; j += 8) {
        int e = e0 + ty + j, t = t0 + tx;
        float v = tile[tx][ty + j];
        __nv_bfloat16 h = __float2bfloat16(v);
        __nv_bfloat16 l = __float2bfloat16(v - __bfloat162float(h));
        __nv_bfloat16* row = Vts + ((long)b * EE + e) * KAV;
        row[t]          = h;
        row[SS + t]     = h;
        row[2*SS + t]   = l;
    }
}

// ---------------------------------------------------------------------------
// wmma (HMMA) GEMM: C[.,1024] = A'[M,K'] x B'[1024,K']^T (+bias), batched via z.
// BM=BN=128, BK=32, 128 threads (4 warps, 2x2), warp tile 64x64 (4x4 frags),
// double-buffered cp.async. lda = K' (row stride of both A' and B').
// ---------------------------------------------------------------------------
#define WG_LDS   40                  // smem row stride (bf16 elems), 80 bytes
#define WG_BUF   (128 * WG_LDS * 2)  // 10240 bytes per tile

__global__ __launch_bounds__(128) void wgemm_kernel(
    const __nv_bfloat16* __restrict__ A, const __nv_bfloat16* __restrict__ B,
    const float* __restrict__ bias, float* __restrict__ C,
    int lda, int nch, long sA, long sB, long sC) {
    __shared__ __align__(16) char smem_raw[4 * WG_BUF];  // A0,B0,A1,B1 = 40960 B
    uint32_t sbase = smem_u32(smem_raw);

    int tid  = threadIdx.x;
    int wid  = tid >> 5, lane = tid & 31;
    int wm   = wid >> 1;        // warp row: rows [wm*64, wm*64+64)
    int wn   = wid & 1;         // warp col: cols [wn*64, wn*64+64)

    long bz = blockIdx.z;
    const __nv_bfloat16* Ab = A + bz * sA;
    const __nv_bfloat16* Bb = B + bz * sB;
    float* Cb = C + bz * sC;

    long m0 = (long)blockIdx.y * 128;
    int  n0 = blockIdx.x * 128;

    // cp.async mapping: A tile 128x32 bf16 = 512 x 16B segs; 4 per thread. Same for B.
    uint32_t dstO[4];
    const char* srcA[4];
    const char* srcB[4];
    #pragma unroll
    for (int u = 0; u < 4; u++) {
        int idx = tid + 128 * u;
        int row = idx >> 2, seg = idx & 3;
        dstO[u] = (uint32_t)row * (WG_LDS * 2) + seg * 16;
        srcA[u] = (const char*)(Ab + (m0 + row) * (long)lda) + seg * 16;
        srcB[u] = (const char*)(Bb + (long)(n0 + row) * lda) + seg * 16;
    }

    wmma::fragment<wmma::accumulator, 16, 16, 16, float> acc[4][4];
    #pragma unroll
    for (int i = 0; i < 4; i++)
        #pragma unroll
        for (int j = 0; j < 4; j++) wmma::fill_fragment(acc[i][j], 0.f);

    // prologue: chunk 0 -> buf 0
    #pragma unroll
    for (int u = 0; u < 4; u++) {
        cp16(sbase + dstO[u], srcA[u]);
        cp16(sbase + WG_BUF + dstO[u], srcB[u]);
    }
    CP_COMMIT();

    #pragma unroll 1
    for (int ch = 0; ch < nch; ch++) {
        if (ch + 1 < nch) {
            uint32_t off = ((ch + 1) & 1) ? 2u * WG_BUF : 0u;
            long gofs = (long)(ch + 1) * 64;   // 32 bf16 = 64 bytes per chunk
            #pragma unroll
            for (int u = 0; u < 4; u++) {
                cp16(sbase + off + dstO[u], srcA[u] + gofs);
                cp16(sbase + off + WG_BUF + dstO[u], srcB[u] + gofs);
            }
            CP_COMMIT();
            CP_WAIT1();
        } else {
            CP_WAIT0();
        }
        __syncthreads();

        const __nv_bfloat16* bufA =
            (const __nv_bfloat16*)(smem_raw + ((ch & 1) ? 2 * WG_BUF : 0));
        const __nv_bfloat16* bufB = bufA + 128 * WG_LDS;

        #pragma unroll
        for (int kk = 0; kk < 32; kk += 16) {
            wmma::fragment<wmma::matrix_a, 16, 16, 16, __nv_bfloat16, wmma::row_major> af[4];
            #pragma unroll
            for (int i = 0; i < 4; i++)
                wmma::load_matrix_sync(af[i], bufA + (wm * 64 + i * 16) * WG_LDS + kk, WG_LDS);
            #pragma unroll
            for (int j = 0; j < 4; j++) {
                wmma::fragment<wmma::matrix_b, 16, 16, 16, __nv_bfloat16, wmma::col_major> bf;
                wmma::load_matrix_sync(bf, bufB + (wn * 64 + j * 16) * WG_LDS + kk, WG_LDS);
                #pragma unroll
                for (int i = 0; i < 4; i++)
                    wmma::mma_sync(acc[i][j], af[i], bf, acc[i][j]);
            }
        }
        __syncthreads();
    }

    // Epilogue: per-warp SMEM staging (16x68 f32) -> coalesced STG (+bias)
    __syncthreads();
    float* stag = (float*)smem_raw + wid * (16 * 68);   // 4 warps x 4352B = 17408
    int erow = lane >> 1, ecb = (lane & 1) * 32;
    #pragma unroll
    for (int mi = 0; mi < 4; mi++) {
        #pragma unroll
        for (int j = 0; j < 4; j++)
            wmma::store_matrix_sync(stag + j * 16, acc[mi][j], 68, wmma::mem_row_major);
        __syncwarp();
        long grow = m0 + wm * 64 + mi * 16 + erow;
        int  gcol = n0 + wn * 64 + ecb;
        #pragma unroll
        for (int f = 0; f < 8; f++) {
            float4 v = *(float4*)(stag + erow * 68 + ecb + f * 4);
            if (bias) {
                float4 b4 = *(const float4*)(bias + gcol + f * 4);
                v.x += b4.x; v.y += b4.y; v.z += b4.z; v.w += b4.w;
            }
            *(float4*)(Cb + grow * EE + gcol + f * 4) = v;
        }
        __syncwarp();
    }
}

// ---------------------------------------------------------------------------
// qin = X @ Wi + bi    (16384x8, K=1024) : one warp per row
// ---------------------------------------------------------------------------
__global__ __launch_bounds__(256) void qin_kernel(const float* __restrict__ X,
                                                  const float* __restrict__ Wi,
                                                  const float* __restrict__ bi) {
    __shared__ float sWi[NQ * EE];
    int tid = threadIdx.x;
    for (int idx = tid; idx < EE * NQ; idx += 256) {
        int k = idx >> 3, o = idx & 7;
        sWi[o * EE + k] = Wi[idx];
    }
    __syncthreads();

    int w = tid >> 5, lane = tid & 31;
    long row = (long)blockIdx.x * 8 + w;
    const float* xr = X + row * EE;

    float acc[NQ];
    #pragma unroll
    for (int o = 0; o < NQ; o++) acc[o] = 0.f;
    for (int k = lane; k < EE; k += 32) {
        float x = xr[k];
        #pragma unroll
        for (int o = 0; o < NQ; o++) acc[o] += x * sWi[o * EE + k];
    }
    float out = 0.f;
    #pragma unroll
    for (int o = 0; o < NQ; o++) {
        float v = acc[o];
        #pragma unroll
        for (int d = 16; d > 0; d >>= 1) v += __shfl_xor_sync(FULLM, v, d);
        if (lane == o) out = v + bi[o];
    }
    if (lane < NQ) d_qin[row * NQ + lane] = out;
}

// ---------------------------------------------------------------------------
// Quantum state sim: one warp per row, state (256 complex) in shared
// ---------------------------------------------------------------------------
__global__ __launch_bounds__(256) void psi_kernel() {
    __shared__ float2 st[8][DIMQ];
    __shared__ float2 gm[NL * NQ * 4];
    __shared__ int    pm[DIMQ];

    int tid = threadIdx.x;
    if (tid < NL * NQ * 4) gm[tid] = d_gates[tid];
    pm[tid] = d_perm[tid];
    __syncthreads();

    int w = tid >> 5, lane = tid & 31;
    long row = (long)blockIdx.x * 8 + w;

    float x = (lane < NQ) ? d_qin[row * NQ + lane] : 0.f;
    float ss, cc;
    sincosf(0.5f * x, &ss, &cc);
    float cq[NQ], sq[NQ];
    #pragma unroll
    for (int q = 0; q < NQ; q++) {
        cq[q] = __shfl_sync(FULLM, cc, q);
        sq[q] = __shfl_sync(FULLM, ss, q);
    }
    #pragma unroll
    for (int j = 0; j < 8; j++) {
        int i = lane + 32 * j;
        float a = 1.f;
        #pragma unroll
        for (int q = 0; q < NQ; q++)
            a *= ((i >> (NQ - 1 - q)) & 1) ? sq[q] : cq[q];
        st[w][i] = make_float2(a, 0.f);
    }
    __syncwarp();

    for (int l = 0; l < NL; l++) {
        #pragma unroll
        for (int q = 0; q < NQ; q++) {
            const float2 m00 = gm[(l * NQ + q) * 4 + 0];
            const float2 m01 = gm[(l * NQ + q) * 4 + 1];
            const float2 m10 = gm[(l * NQ + q) * 4 + 2];
            const float2 m11 = gm[(l * NQ + q) * 4 + 3];
            int stride = 1 << (NQ - 1 - q);
            #pragma unroll
            for (int pp = 0; pp < 4; pp++) {
                int p  = lane + 32 * pp;
                int i0 = ((p & ~(stride - 1)) << 1) | (p & (stride - 1));
                int i1 = i0 | stride;
                float2 a0 = st[w][i0];
                float2 a1 = st[w][i1];
                float2 n0, n1;
                n0.x = m00.x * a0.x - m00.y * a0.y + m01.x * a1.x - m01.y * a1.y;
                n0.y = m00.x * a0.y + m00.y * a0.x + m01.x * a1.y + m01.y * a1.x;
                n1.x = m10.x * a0.x - m10.y * a0.y + m11.x * a1.x - m11.y * a1.y;
                n1.y = m10.x * a0.y + m10.y * a0.x + m11.x * a1.y + m11.y * a1.x;
                st[w][i0] = n0;
                st[w][i1] = n1;
            }
            __syncwarp();
        }
        float2 tmp[8];
        #pragma unroll
        for (int j = 0; j < 8; j++) tmp[j] = st[w][pm[lane + 32 * j]];
        __syncwarp();
        #pragma unroll
        for (int j = 0; j < 8; j++) st[w][lane + 32 * j] = tmp[j];
        __syncwarp();
    }
    #pragma unroll
    for (int j = 0; j < 8; j++)
        d_psi[row * DIMQ + lane + 32 * j] = st[w][lane + 32 * j];
}

// ---------------------------------------------------------------------------
// Gram + kernel-matrix + softmax -> attn.  One block per batch, 512 threads.
// ---------------------------------------------------------------------------
__global__ __launch_bounds__(512) void gram_kernel(const float* __restrict__ phi,
                                                   float* __restrict__ attn) {
    const int DC = 16;
    __shared__ float2 P[SS][DC + 1];

    int b   = blockIdx.x;
    int tid = threadIdx.x;
    int ts  = tid >> 5;
    int tt  = tid & 31;

    float accr[8][4], acci[8][4];
    #pragma unroll
    for (int j = 0; j < 8; j++)
        #pragma unroll
        for (int k = 0; k < 4; k++) { accr[j][k] = 0.f; acci[j][k] = 0.f; }

    const float2* pb = d_psi + (long)b * SS * DIMQ;

    for (int d0 = 0; d0 < DIMQ; d0 += DC) {
        #pragma unroll
        for (int u = 0; u < 4; u++) {
            int idx = tid + 512 * u;
            int r = idx >> 4, dd = idx & 15;
            P[r][dd] = pb[(long)r * DIMQ + d0 + dd];
        }
        __syncthreads();
        #pragma unroll 4
        for (int dd = 0; dd < DC; dd++) {
            float2 sf[8], tf[4];
            #pragma unroll
            for (int j = 0; j < 8; j++) sf[j] = P[ts * 8 + j][dd];
            #pragma unroll
            for (int k = 0; k < 4; k++) tf[k] = P[tt + 32 * k][dd];
            #pragma unroll
            for (int j = 0; j < 8; j++)
                #pragma unroll
                for (int k = 0; k < 4; k++) {
                    accr[j][k] += sf[j].x * tf[k].x + sf[j].y * tf[k].y;
                    acci[j][k] += sf[j].y * tf[k].x - sf[j].x * tf[k].y;
                }
        }
        __syncthreads();
    }

    const float inv = 0.3535533905932738f;
    float pht[4];
    #pragma unroll
    for (int k = 0; k < 4; k++) pht[k] = phi[tt + 32 * k];

    #pragma unroll
    for (int j = 0; j < 8; j++) {
        int srow = ts * 8 + j;
        float ph_s = phi[srow];
        float kv[4];
        float mx = -1e30f;
        #pragma unroll
        for (int k = 0; k < 4; k++) {
            float g2 = accr[j][k] * accr[j][k] + acci[j][k] * acci[j][k];
            kv[k] = g2 * inv + cosf(pht[k] - ph_s);
            mx = fmaxf(mx, kv[k]);
        }
        #pragma unroll
        for (int d = 16; d > 0; d >>= 1) mx = fmaxf(mx, __shfl_xor_sync(FULLM, mx, d));
        float sum = 0.f;
        #pragma unroll
        for (int k = 0; k < 4; k++) { kv[k] = expf(kv[k] - mx); sum += kv[k]; }
        #pragma unroll
        for (int d = 16; d > 0; d >>= 1) sum += __shfl_xor_sync(FULLM, sum, d);
        float is = 1.f / sum;
        #pragma unroll
        for (int k = 0; k < 4; k++)
            attn[(long)b * SS * SS + (long)srow * SS + tt + 32 * k] = kv[k] * is;
    }
}

// ---------------------------------------------------------------------------
extern "C" void kernel_launch(void* const* d_in, const int* in_sizes, int n_in,
                              void* d_out, int out_size) {
    const float* X     = (const float*)d_in[0];
    const float* Wi    = (const float*)d_in[1];
    const float* bi    = (const float*)d_in[2];
    const float* Wv    = (const float*)d_in[3];
    const float* bv    = (const float*)d_in[4];
    const float* Wo    = (const float*)d_in[5];
    const float* bo    = (const float*)d_in[6];
    const float* theta = (const float*)d_in[7];
    const float* phi   = (const float*)d_in[8];

    float* y    = (float*)d_out;
    float* attn = (float*)d_out + Y_SIZE;

    float *pV, *pT;
    __nv_bfloat16 *pXs, *pTs, *pWvs, *pWos, *pAs, *pVts;
    cudaGetSymbolAddress((void**)&pV, d_V);
    cudaGetSymbolAddress((void**)&pT, d_T);
    cudaGetSymbolAddress((void**)&pXs, d_Xs);
    cudaGetSymbolAddress((void**)&pTs, d_Ts);
    cudaGetSymbolAddress((void**)&pWvs, d_Wvs);
    cudaGetSymbolAddress((void**)&pWos, d_Wos);
    cudaGetSymbolAddress((void**)&pAs, d_attns);
    cudaGetSymbolAddress((void**)&pVts, d_Vts);

    // prep + splits
    prep_kernel<<<1, 256>>>(theta);
    {
        dim3 g(EE / 32, EE / 32);
        splitB_kernel<<<g, 256>>>(Wv, pWvs);
        splitB_kernel<<<g, 256>>>(Wo, pWos);
    }
    splitA_kernel<<<ROWS, 256>>>(X, pXs);
    qin_kernel<<<ROWS / 8, 256>>>(X, Wi, bi);

    // V = X@Wv + bv  (wmma)
    {
        dim3 grid(EE / 128, ROWS / 128, 1);
        wgemm_kernel<<<grid, 128>>>(pXs, pWvs, bv, pV, KSPLIT, KSPLIT / 32, 0, 0, 0);
    }

    // quantum states + Gram/softmax
    psi_kernel<<<ROWS / 8, 256>>>();
    gram_kernel<<<NB, 512>>>(phi, attn);

    // splits for attn@V
    {
        dim3 g(EE / 32, SS / 32, NB);
        splitVt_kernel<<<g, 256>>>(pV, pVts);
    }
    splitAttn_kernel<<<ROWS * 32 / 256, 256>>>(attn, pAs);

    // T = attn @ V (wmma, batched over z)
    {
        dim3 grid(EE / 128, 1, NB);
        wgemm_kernel<<<grid, 128>>>(pAs, pVts, nullptr, pT, KAV, KAV / 32,
                                    (long)SS * KAV, (long)EE * KAV, (long)SS * EE);
    }

    // split T, then y = T@Wo + bo (wmma)
    splitA_kernel<<<ROWS, 256>>>(pT, pTs);
    {
        dim3 grid(EE / 128, ROWS / 128, 1);
        wgemm_kernel<<<grid, 128>>>(pTs, pWos, bo, y, KSPLIT, KSPLIT / 32, 0, 0, 0);
    }
}

// round 9
// speedup vs baseline: 1.0260x; 1.0260x over previous
#include <cuda_runtime.h>
#include <cuda_bf16.h>
#include <mma.h>
#include <math.h>
#include <stdint.h>

using namespace nvcuda;

// Problem constants (fixed shapes)
#define NB      128          // batch
#define SS      128          // seq
#define EE      1024         // embed
#define NQ      8            // qubits
#define NL      4            // layers
#define DIMQ    256          // 2^NQ
#define ROWS    16384        // NB*SS
#define KSPLIT  3072         // 3*EE (bf16 split-concat K)
#define KAV     384          // 3*SS  (attn@V split K)
#define Y_SIZE  16777216L    // NB*SS*EE

// Scratch (static device globals — allowed)
__device__ float  d_qin[ROWS * NQ];
__device__ float2 d_gates[NL * NQ * 4];
__device__ int    d_perm[DIMQ];
__device__ float2 d_psi[(long)ROWS * DIMQ];
__device__ float  d_V[(long)ROWS * EE];
__device__ float  d_T[(long)ROWS * EE];
__device__ __nv_bfloat16 d_Xs[(long)ROWS * KSPLIT];    // split X    [M][3K]
__device__ __nv_bfloat16 d_Ts[(long)ROWS * KSPLIT];    // split T    [M][3K]
__device__ __nv_bfloat16 d_Wvs[(long)EE * KSPLIT];     // split Wv^T [N][3K]
__device__ __nv_bfloat16 d_Wos[(long)EE * KSPLIT];     // split Wo^T [N][3K]
__device__ __nv_bfloat16 d_attns[(long)ROWS * KAV];    // split attn [b*s][3*128]
__device__ __nv_bfloat16 d_Vts[(long)NB * EE * KAV];   // split V^T  [b][e][3*128]

#define FULLM 0xffffffffu

// ---------------------------------------------------------------------------
// cp.async helpers (sm_80+ baseline — no 'a'-suffix features!)
// ---------------------------------------------------------------------------
__device__ __forceinline__ uint32_t smem_u32(const void* p) {
    uint32_t a;
    asm("{ .reg .u64 t; cvta.to.shared.u64 t, %1; cvt.u32.u64 %0, t; }" : "=r"(a) : "l"(p));
    return a;
}
__device__ __forceinline__ void cp16(uint32_t s, const void* g) {
    asm volatile("cp.async.cg.shared.global [%0], [%1], 16;" :: "r"(s), "l"(g));
}
#define CP_COMMIT() asm volatile("cp.async.commit_group;" ::: "memory")
#define CP_WAIT1()  asm volatile("cp.async.wait_group 1;" ::: "memory")
#define CP_WAIT0()  asm volatile("cp.async.wait_group 0;" ::: "memory")

// ---------------------------------------------------------------------------
// Prep: fused RZ*RY gate matrices, composed CNOT-ring perm
// ---------------------------------------------------------------------------
__global__ void prep_kernel(const float* __restrict__ theta) {
    int t = threadIdx.x;
    if (t < NL * NQ) {
        float ty = theta[t * 2 + 0];
        float tz = theta[t * 2 + 1];
        float s, c, zs, zc;
        sincosf(0.5f * ty, &s, &c);
        sincosf(0.5f * tz, &zs, &zc);
        d_gates[t * 4 + 0] = make_float2( c * zc, -c * zs);
        d_gates[t * 4 + 1] = make_float2(-s * zc,  s * zs);
        d_gates[t * 4 + 2] = make_float2( s * zc,  s * zs);
        d_gates[t * 4 + 3] = make_float2( c * zc,  c * zs);
    }
    if (t < DIMQ) {
        int j = t;
        #pragma unroll
        for (int q = NQ - 1; q >= 0; q--) {
            int tq   = (q + 1) & (NQ - 1);
            int cpos = NQ - 1 - q;
            int tpos = NQ - 1 - tq;
            if ((j >> cpos) & 1) j ^= (1 << tpos);
        }
        d_perm[t] = j;
    }
}

// ---------------------------------------------------------------------------
// splitA: fp32 [R x 1024] -> bf16 [R x 3072] laid out [hi | lo | hi]
// ---------------------------------------------------------------------------
__global__ __launch_bounds__(256) void splitA_kernel(const float* __restrict__ src,
                                                     __nv_bfloat16* __restrict__ dst) {
    long i = (long)blockIdx.x * 256 + threadIdx.x;   // float4 index
    float4 v = ((const float4*)src)[i];
    long r  = i >> 8;
    int  c4 = (int)(i & 255) * 4;
    float vv[4] = {v.x, v.y, v.z, v.w};
    union { __nv_bfloat16 b[4]; uint2 u; } H, L;
    #pragma unroll
    for (int j = 0; j < 4; j++) {
        __nv_bfloat16 h = __float2bfloat16(vv[j]);
        H.b[j] = h;
        L.b[j] = __float2bfloat16(vv[j] - __bfloat162float(h));
    }
    __nv_bfloat16* row = dst + r * KSPLIT;
    *(uint2*)(row + c4)        = H.u;
    *(uint2*)(row + EE + c4)   = L.u;
    *(uint2*)(row + 2*EE + c4) = H.u;
}

// ---------------------------------------------------------------------------
// splitAttn: attn fp32 [16384 x 128] -> bf16 [16384 x 384] = [hi | lo | hi]
// ---------------------------------------------------------------------------
__global__ __launch_bounds__(256) void splitAttn_kernel(const float* __restrict__ src,
                                                        __nv_bfloat16* __restrict__ dst) {
    long i = (long)blockIdx.x * 256 + threadIdx.x;   // float4 index (16384*32 total)
    float4 v = ((const float4*)src)[i];
    long r  = i >> 5;
    int  c4 = (int)(i & 31) * 4;
    float vv[4] = {v.x, v.y, v.z, v.w};
    union { __nv_bfloat16 b[4]; uint2 u; } H, L;
    #pragma unroll
    for (int j = 0; j < 4; j++) {
        __nv_bfloat16 h = __float2bfloat16(vv[j]);
        H.b[j] = h;
        L.b[j] = __float2bfloat16(vv[j] - __bfloat162float(h));
    }
    __nv_bfloat16* row = dst + r * KAV;
    *(uint2*)(row + c4)          = H.u;
    *(uint2*)(row + SS + c4)     = L.u;
    *(uint2*)(row + 2*SS + c4)   = H.u;
}

// ---------------------------------------------------------------------------
// splitB: W fp32 [K=1024][N=1024] -> Bt bf16 [N][3072] = [hi | hi | lo] transposed
// ---------------------------------------------------------------------------
__global__ __launch_bounds__(256) void splitB_kernel(const float* __restrict__ W,
                                                     __nv_bfloat16* __restrict__ Bt) {
    __shared__ float tile[32][33];
    int k0 = blockIdx.y * 32, n0 = blockIdx.x * 32;
    int tx = threadIdx.x & 31, ty = threadIdx.x >> 5;  // 32 x 8
    #pragma unroll
    for (int j = 0; j < 32; j += 8)
        tile[ty + j][tx] = W[(long)(k0 + ty + j) * EE + n0 + tx];
    __syncthreads();
    #pragma unroll
    for (int j = 0; j < 32; j += 8) {
        int n = n0 + ty + j, k = k0 + tx;
        float v = tile[tx][ty + j];
        __nv_bfloat16 h = __float2bfloat16(v);
        __nv_bfloat16 l = __float2bfloat16(v - __bfloat162float(h));
        __nv_bfloat16* row = Bt + (long)n * KSPLIT;
        row[k]          = h;
        row[EE + k]     = h;
        row[2*EE + k]   = l;
    }
}

// ---------------------------------------------------------------------------
// splitVt: V fp32 [b*128+t][e] -> Vts bf16 [b][e][384] = [hi(t) | hi(t) | lo(t)]
// ---------------------------------------------------------------------------
__global__ __launch_bounds__(256) void splitVt_kernel(const float* __restrict__ V,
                                                      __nv_bfloat16* __restrict__ Vts) {
    __shared__ float tile[32][33];
    int b  = blockIdx.z;
    int t0 = blockIdx.y * 32, e0 = blockIdx.x * 32;
    int tx = threadIdx.x & 31, ty = threadIdx.x >> 5;  // 32 x 8
    #pragma unroll
    for (int j = 0; j < 32; j += 8)
        tile[ty + j][tx] = V[((long)b * SS + t0 + ty + j) * EE + e0 + tx];  // tile[t][e]
    __syncthreads();
    #pragma unroll
    for (int j = 0; j < 32; j += 8) {
        int e = e0 + ty + j, t = t0 + tx;
        float v = tile[tx][ty + j];
        __nv_bfloat16 h = __float2bfloat16(v);
        __nv_bfloat16 l = __float2bfloat16(v - __bfloat162float(h));
        __nv_bfloat16* row = Vts + ((long)b * EE + e) * KAV;
        row[t]          = h;
        row[SS + t]     = h;
        row[2*SS + t]   = l;
    }
}

// ---------------------------------------------------------------------------
// wmma (HMMA) GEMM: C[.,1024] = A'[M,K'] x B'[1024,K']^T (+bias), batched via z.
// BM=BN=128, BK=32, 256 threads (8 warps, 4x2), warp tile 32x64 (2x4 frags),
// double-buffered cp.async.  [R6 measured-good geometry]
// ---------------------------------------------------------------------------
#define WG_LDS   40                  // smem row stride (bf16 elems), 80 bytes
#define WG_BUF   (128 * WG_LDS * 2)  // 10240 bytes per tile

__global__ __launch_bounds__(256) void wgemm_kernel(
    const __nv_bfloat16* __restrict__ A, const __nv_bfloat16* __restrict__ B,
    const float* __restrict__ bias, float* __restrict__ C,
    int lda, int nch, long sA, long sB, long sC) {
    __shared__ __align__(16) char smem_raw[4 * WG_BUF];  // A0,B0,A1,B1 = 40960 B
    uint32_t sbase = smem_u32(smem_raw);

    int tid  = threadIdx.x;
    int wid  = tid >> 5, lane = tid & 31;
    int wm   = wid & 3;         // warp row: rows [wm*32, wm*32+32)
    int wn   = wid >> 2;        // warp col: cols [wn*64, wn*64+64)

    long bz = blockIdx.z;
    const __nv_bfloat16* Ab = A + bz * sA;
    const __nv_bfloat16* Bb = B + bz * sB;
    float* Cb = C + bz * sC;

    long m0 = (long)blockIdx.y * 128;
    int  n0 = blockIdx.x * 128;

    // cp.async mapping: tile 128x32 bf16 = 512 x 16B segs; 2 per thread per matrix.
    uint32_t dstO[2];
    const char* srcA[2];
    const char* srcB[2];
    #pragma unroll
    for (int u = 0; u < 2; u++) {
        int idx = tid + 256 * u;
        int row = idx >> 2, seg = idx & 3;
        dstO[u] = (uint32_t)row * (WG_LDS * 2) + seg * 16;
        srcA[u] = (const char*)(Ab + (m0 + row) * (long)lda) + seg * 16;
        srcB[u] = (const char*)(Bb + (long)(n0 + row) * lda) + seg * 16;
    }

    wmma::fragment<wmma::accumulator, 16, 16, 16, float> acc[2][4];
    #pragma unroll
    for (int i = 0; i < 2; i++)
        #pragma unroll
        for (int j = 0; j < 4; j++) wmma::fill_fragment(acc[i][j], 0.f);

    // prologue: chunk 0 -> buf 0
    #pragma unroll
    for (int u = 0; u < 2; u++) {
        cp16(sbase + dstO[u], srcA[u]);
        cp16(sbase + WG_BUF + dstO[u], srcB[u]);
    }
    CP_COMMIT();

    #pragma unroll 1
    for (int ch = 0; ch < nch; ch++) {
        if (ch + 1 < nch) {
            uint32_t off = ((ch + 1) & 1) ? 2u * WG_BUF : 0u;
            long gofs = (long)(ch + 1) * 64;   // 32 bf16 = 64 bytes per chunk
            #pragma unroll
            for (int u = 0; u < 2; u++) {
                cp16(sbase + off + dstO[u], srcA[u] + gofs);
                cp16(sbase + off + WG_BUF + dstO[u], srcB[u] + gofs);
            }
            CP_COMMIT();
            CP_WAIT1();
        } else {
            CP_WAIT0();
        }
        __syncthreads();

        const __nv_bfloat16* bufA =
            (const __nv_bfloat16*)(smem_raw + ((ch & 1) ? 2 * WG_BUF : 0));
        const __nv_bfloat16* bufB = bufA + 128 * WG_LDS;

        #pragma unroll
        for (int kk = 0; kk < 32; kk += 16) {
            wmma::fragment<wmma::matrix_a, 16, 16, 16, __nv_bfloat16, wmma::row_major> af[2];
            wmma::fragment<wmma::matrix_b, 16, 16, 16, __nv_bfloat16, wmma::col_major> bf[4];
            #pragma unroll
            for (int i = 0; i < 2; i++)
                wmma::load_matrix_sync(af[i], bufA + (wm * 32 + i * 16) * WG_LDS + kk, WG_LDS);
            #pragma unroll
            for (int j = 0; j < 4; j++)
                wmma::load_matrix_sync(bf[j], bufB + (wn * 64 + j * 16) * WG_LDS + kk, WG_LDS);
            #pragma unroll
            for (int i = 0; i < 2; i++)
                #pragma unroll
                for (int j = 0; j < 4; j++)
                    wmma::mma_sync(acc[i][j], af[i], bf[j], acc[i][j]);
        }
        __syncthreads();
    }

    // Epilogue: per-warp SMEM staging (16x68 f32) -> coalesced STG (+bias)
    float* stag = (float*)smem_raw + wid * (16 * 68);   // 8 warps x 4352B = 34816
    int erow = lane >> 1, ecb = (lane & 1) * 32;
    #pragma unroll
    for (int mi = 0; mi < 2; mi++) {
        #pragma unroll
        for (int j = 0; j < 4; j++)
            wmma::store_matrix_sync(stag + j * 16, acc[mi][j], 68, wmma::mem_row_major);
        __syncwarp();
        long grow = m0 + wm * 32 + mi * 16 + erow;
        int  gcol = n0 + wn * 64 + ecb;
        #pragma unroll
        for (int f = 0; f < 8; f++) {
            float4 v = *(float4*)(stag + erow * 68 + ecb + f * 4);
            if (bias) {
                float4 b4 = *(const float4*)(bias + gcol + f * 4);
                v.x += b4.x; v.y += b4.y; v.z += b4.z; v.w += b4.w;
            }
            *(float4*)(Cb + grow * EE + gcol + f * 4) = v;
        }
        __syncwarp();
    }
}

// ---------------------------------------------------------------------------
// qin = X @ Wi + bi    (16384x8, K=1024) : one warp per row
// ---------------------------------------------------------------------------
__global__ __launch_bounds__(256) void qin_kernel(const float* __restrict__ X,
                                                  const float* __restrict__ Wi,
                                                  const float* __restrict__ bi) {
    __shared__ float sWi[NQ * EE];
    int tid = threadIdx.x;
    for (int idx = tid; idx < EE * NQ; idx += 256) {
        int k = idx >> 3, o = idx & 7;
        sWi[o * EE + k] = Wi[idx];
    }
    __syncthreads();

    int w = tid >> 5, lane = tid & 31;
    long row = (long)blockIdx.x * 8 + w;
    const float* xr = X + row * EE;

    float acc[NQ];
    #pragma unroll
    for (int o = 0; o < NQ; o++) acc[o] = 0.f;
    for (int k = lane; k < EE; k += 32) {
        float x = xr[k];
        #pragma unroll
        for (int o = 0; o < NQ; o++) acc[o] += x * sWi[o * EE + k];
    }
    float out = 0.f;
    #pragma unroll
    for (int o = 0; o < NQ; o++) {
        float v = acc[o];
        #pragma unroll
        for (int d = 16; d > 0; d >>= 1) v += __shfl_xor_sync(FULLM, v, d);
        if (lane == o) out = v + bi[o];
    }
    if (lane < NQ) d_qin[row * NQ + lane] = out;
}

// ---------------------------------------------------------------------------
// Quantum state sim: one warp per row, state (256 complex) in shared
// ---------------------------------------------------------------------------
__global__ __launch_bounds__(256) void psi_kernel() {
    __shared__ float2 st[8][DIMQ];
    __shared__ float2 gm[NL * NQ * 4];
    __shared__ int    pm[DIMQ];

    int tid = threadIdx.x;
    if (tid < NL * NQ * 4) gm[tid] = d_gates[tid];
    pm[tid] = d_perm[tid];
    __syncthreads();

    int w = tid >> 5, lane = tid & 31;
    long row = (long)blockIdx.x * 8 + w;

    float x = (lane < NQ) ? d_qin[row * NQ + lane] : 0.f;
    float ss, cc;
    sincosf(0.5f * x, &ss, &cc);
    float cq[NQ], sq[NQ];
    #pragma unroll
    for (int q = 0; q < NQ; q++) {
        cq[q] = __shfl_sync(FULLM, cc, q);
        sq[q] = __shfl_sync(FULLM, ss, q);
    }
    #pragma unroll
    for (int j = 0; j < 8; j++) {
        int i = lane + 32 * j;
        float a = 1.f;
        #pragma unroll
        for (int q = 0; q < NQ; q++)
            a *= ((i >> (NQ - 1 - q)) & 1) ? sq[q] : cq[q];
        st[w][i] = make_float2(a, 0.f);
    }
    __syncwarp();

    for (int l = 0; l < NL; l++) {
        #pragma unroll
        for (int q = 0; q < NQ; q++) {
            const float2 m00 = gm[(l * NQ + q) * 4 + 0];
            const float2 m01 = gm[(l * NQ + q) * 4 + 1];
            const float2 m10 = gm[(l * NQ + q) * 4 + 2];
            const float2 m11 = gm[(l * NQ + q) * 4 + 3];
            int stride = 1 << (NQ - 1 - q);
            #pragma unroll
            for (int pp = 0; pp < 4; pp++) {
                int p  = lane + 32 * pp;
                int i0 = ((p & ~(stride - 1)) << 1) | (p & (stride - 1));
                int i1 = i0 | stride;
                float2 a0 = st[w][i0];
                float2 a1 = st[w][i1];
                float2 n0, n1;
                n0.x = m00.x * a0.x - m00.y * a0.y + m01.x * a1.x - m01.y * a1.y;
                n0.y = m00.x * a0.y + m00.y * a0.x + m01.x * a1.y + m01.y * a1.x;
                n1.x = m10.x * a0.x - m10.y * a0.y + m11.x * a1.x - m11.y * a1.y;
                n1.y = m10.x * a0.y + m10.y * a0.x + m11.x * a1.y + m11.y * a1.x;
                st[w][i0] = n0;
                st[w][i1] = n1;
            }
            __syncwarp();
        }
        float2 tmp[8];
        #pragma unroll
        for (int j = 0; j < 8; j++) tmp[j] = st[w][pm[lane + 32 * j]];
        __syncwarp();
        #pragma unroll
        for (int j = 0; j < 8; j++) st[w][lane + 32 * j] = tmp[j];
        __syncwarp();
    }
    #pragma unroll
    for (int j = 0; j < 8; j++)
        d_psi[row * DIMQ + lane + 32 * j] = st[w][lane + 32 * j];
}

// ---------------------------------------------------------------------------
// Gram + kernel-matrix + softmax -> attn.  One block per batch, 512 threads.
// ---------------------------------------------------------------------------
__global__ __launch_bounds__(512) void gram_kernel(const float* __restrict__ phi,
                                                   float* __restrict__ attn) {
    const int DC = 16;
    __shared__ float2 P[SS][DC + 1];

    int b   = blockIdx.x;
    int tid = threadIdx.x;
    int ts  = tid >> 5;
    int tt  = tid & 31;

    float accr[8][4], acci[8][4];
    #pragma unroll
    for (int j = 0; j < 8; j++)
        #pragma unroll
        for (int k = 0; k < 4; k++) { accr[j][k] = 0.f; acci[j][k] = 0.f; }

    const float2* pb = d_psi + (long)b * SS * DIMQ;

    for (int d0 = 0; d0 < DIMQ; d0 += DC) {
        #pragma unroll
        for (int u = 0; u < 4; u++) {
            int idx = tid + 512 * u;
            int r = idx >> 4, dd = idx & 15;
            P[r][dd] = pb[(long)r * DIMQ + d0 + dd];
        }
        __syncthreads();
        #pragma unroll 4
        for (int dd = 0; dd < DC; dd++) {
            float2 sf[8], tf[4];
            #pragma unroll
            for (int j = 0; j < 8; j++) sf[j] = P[ts * 8 + j][dd];
            #pragma unroll
            for (int k = 0; k < 4; k++) tf[k] = P[tt + 32 * k][dd];
            #pragma unroll
            for (int j = 0; j < 8; j++)
                #pragma unroll
                for (int k = 0; k < 4; k++) {
                    accr[j][k] += sf[j].x * tf[k].x + sf[j].y * tf[k].y;
                    acci[j][k] += sf[j].y * tf[k].x - sf[j].x * tf[k].y;
                }
        }
        __syncthreads();
    }

    const float inv = 0.3535533905932738f;
    float pht[4];
    #pragma unroll
    for (int k = 0; k < 4; k++) pht[k] = phi[tt + 32 * k];

    #pragma unroll
    for (int j = 0; j < 8; j++) {
        int srow = ts * 8 + j;
        float ph_s = phi[srow];
        float kv[4];
        float mx = -1e30f;
        #pragma unroll
        for (int k = 0; k < 4; k++) {
            float g2 = accr[j][k] * accr[j][k] + acci[j][k] * acci[j][k];
            kv[k] = g2 * inv + cosf(pht[k] - ph_s);
            mx = fmaxf(mx, kv[k]);
        }
        #pragma unroll
        for (int d = 16; d > 0; d >>= 1) mx = fmaxf(mx, __shfl_xor_sync(FULLM, mx, d));
        float sum = 0.f;
        #pragma unroll
        for (int k = 0; k < 4; k++) { kv[k] = expf(kv[k] - mx); sum += kv[k]; }
        #pragma unroll
        for (int d = 16; d > 0; d >>= 1) sum += __shfl_xor_sync(FULLM, sum, d);
        float is = 1.f / sum;
        #pragma unroll
        for (int k = 0; k < 4; k++)
            attn[(long)b * SS * SS + (long)srow * SS + tt + 32 * k] = kv[k] * is;
    }
}

// ---------------------------------------------------------------------------
extern "C" void kernel_launch(void* const* d_in, const int* in_sizes, int n_in,
                              void* d_out, int out_size) {
    const float* X     = (const float*)d_in[0];
    const float* Wi    = (const float*)d_in[1];
    const float* bi    = (const float*)d_in[2];
    const float* Wv    = (const float*)d_in[3];
    const float* bv    = (const float*)d_in[4];
    const float* Wo    = (const float*)d_in[5];
    const float* bo    = (const float*)d_in[6];
    const float* theta = (const float*)d_in[7];
    const float* phi   = (const float*)d_in[8];

    float* y    = (float*)d_out;
    float* attn = (float*)d_out + Y_SIZE;

    float *pV, *pT;
    __nv_bfloat16 *pXs, *pTs, *pWvs, *pWos, *pAs, *pVts;
    cudaGetSymbolAddress((void**)&pV, d_V);
    cudaGetSymbolAddress((void**)&pT, d_T);
    cudaGetSymbolAddress((void**)&pXs, d_Xs);
    cudaGetSymbolAddress((void**)&pTs, d_Ts);
    cudaGetSymbolAddress((void**)&pWvs, d_Wvs);
    cudaGetSymbolAddress((void**)&pWos, d_Wos);
    cudaGetSymbolAddress((void**)&pAs, d_attns);
    cudaGetSymbolAddress((void**)&pVts, d_Vts);

    // prep + splits
    prep_kernel<<<1, 256>>>(theta);
    {
        dim3 g(EE / 32, EE / 32);
        splitB_kernel<<<g, 256>>>(Wv, pWvs);
        splitB_kernel<<<g, 256>>>(Wo, pWos);
    }
    splitA_kernel<<<ROWS, 256>>>(X, pXs);
    qin_kernel<<<ROWS / 8, 256>>>(X, Wi, bi);

    // V = X@Wv + bv  (wmma)
    {
        dim3 grid(EE / 128, ROWS / 128, 1);
        wgemm_kernel<<<grid, 256>>>(pXs, pWvs, bv, pV, KSPLIT, KSPLIT / 32, 0, 0, 0);
    }

    // quantum states + Gram/softmax
    psi_kernel<<<ROWS / 8, 256>>>();
    gram_kernel<<<NB, 512>>>(phi, attn);

    // splits for attn@V
    {
        dim3 g(EE / 32, SS / 32, NB);
        splitVt_kernel<<<g, 256>>>(pV, pVts);
    }
    splitAttn_kernel<<<ROWS * 32 / 256, 256>>>(attn, pAs);

    // T = attn @ V (wmma, batched over z)
    {
        dim3 grid(EE / 128, 1, NB);
        wgemm_kernel<<<grid, 256>>>(pAs, pVts, nullptr, pT, KAV, KAV / 32,
                                    (long)SS * KAV, (long)EE * KAV, (long)SS * EE);
    }

    // split T, then y = T@Wo + bo (wmma)
    splitA_kernel<<<ROWS, 256>>>(pT, pTs);
    {
        dim3 grid(EE / 128, ROWS / 128, 1);
        wgemm_kernel<<<grid, 256>>>(pTs, pWos, bo, y, KSPLIT, KSPLIT / 32, 0, 0, 0);
    }
}

// round 10
// speedup vs baseline: 1.4118x; 1.3761x over previous
#include <cuda_runtime.h>
#include <cuda_fp16.h>
#include <mma.h>
#include <math.h>
#include <stdint.h>

using namespace nvcuda;

// Problem constants (fixed shapes)
#define NB      128          // batch
#define SS      128          // seq
#define EE      1024         // embed
#define NQ      8            // qubits
#define NL      4            // layers
#define DIMQ    256          // 2^NQ
#define ROWS    16384        // NB*SS
#define KSPLIT  2048         // 2*EE  (fp16 2-term split: A=[hi|lo], B=[hi|hi])
#define KAV     256          // 2*SS  (attn@V split K)
#define Y_SIZE  16777216L    // NB*SS*EE

// Scratch (static device globals — allowed)
__device__ float  d_qin[ROWS * NQ];
__device__ float2 d_gates[NL * NQ * 4];
__device__ int    d_perm[DIMQ];
__device__ float2 d_psi[(long)ROWS * DIMQ];
__device__ float  d_V[(long)ROWS * EE];
__device__ float  d_T[(long)ROWS * EE];
__device__ __half d_Xs[(long)ROWS * KSPLIT];    // split X    [M][2K]
__device__ __half d_Ts[(long)ROWS * KSPLIT];    // split T    [M][2K]
__device__ __half d_Wvs[(long)EE * KSPLIT];     // Wv^T       [N][2K] = [hi|hi]
__device__ __half d_Wos[(long)EE * KSPLIT];     // Wo^T       [N][2K] = [hi|hi]
__device__ __half d_attns[(long)ROWS * KAV];    // split attn [b*s][2*128]
__device__ __half d_Vts[(long)NB * EE * KAV];   // V^T        [b][e][2*128] = [hi|hi]

#define FULLM 0xffffffffu

// ---------------------------------------------------------------------------
// cp.async helpers (sm_80+ baseline — no 'a'-suffix features!)
// ---------------------------------------------------------------------------
__device__ __forceinline__ uint32_t smem_u32(const void* p) {
    uint32_t a;
    asm("{ .reg .u64 t; cvta.to.shared.u64 t, %1; cvt.u32.u64 %0, t; }" : "=r"(a) : "l"(p));
    return a;
}
__device__ __forceinline__ void cp16(uint32_t s, const void* g) {
    asm volatile("cp.async.cg.shared.global [%0], [%1], 16;" :: "r"(s), "l"(g));
}
#define CP_COMMIT() asm volatile("cp.async.commit_group;" ::: "memory")
#define CP_WAIT1()  asm volatile("cp.async.wait_group 1;" ::: "memory")
#define CP_WAIT0()  asm volatile("cp.async.wait_group 0;" ::: "memory")

// ---------------------------------------------------------------------------
// Prep: fused RZ*RY gate matrices, composed CNOT-ring perm
// ---------------------------------------------------------------------------
__global__ void prep_kernel(const float* __restrict__ theta) {
    int t = threadIdx.x;
    if (t < NL * NQ) {
        float ty = theta[t * 2 + 0];
        float tz = theta[t * 2 + 1];
        float s, c, zs, zc;
        sincosf(0.5f * ty, &s, &c);
        sincosf(0.5f * tz, &zs, &zc);
        d_gates[t * 4 + 0] = make_float2( c * zc, -c * zs);
        d_gates[t * 4 + 1] = make_float2(-s * zc,  s * zs);
        d_gates[t * 4 + 2] = make_float2( s * zc,  s * zs);
        d_gates[t * 4 + 3] = make_float2( c * zc,  c * zs);
    }
    if (t < DIMQ) {
        int j = t;
        #pragma unroll
        for (int q = NQ - 1; q >= 0; q--) {
            int tq   = (q + 1) & (NQ - 1);
            int cpos = NQ - 1 - q;
            int tpos = NQ - 1 - tq;
            if ((j >> cpos) & 1) j ^= (1 << tpos);
        }
        d_perm[t] = j;
    }
}

// ---------------------------------------------------------------------------
// splitA: fp32 [R x 1024] -> fp16 [R x 2048] laid out [hi | lo]
// ---------------------------------------------------------------------------
__global__ __launch_bounds__(256) void splitA_kernel(const float* __restrict__ src,
                                                     __half* __restrict__ dst) {
    long i = (long)blockIdx.x * 256 + threadIdx.x;   // float4 index
    float4 v = ((const float4*)src)[i];
    long r  = i >> 8;
    int  c4 = (int)(i & 255) * 4;
    float vv[4] = {v.x, v.y, v.z, v.w};
    union { __half b[4]; uint2 u; } H, L;
    #pragma unroll
    for (int j = 0; j < 4; j++) {
        __half h = __float2half(vv[j]);
        H.b[j] = h;
        L.b[j] = __float2half(vv[j] - __half2float(h));
    }
    __half* row = dst + r * KSPLIT;
    *(uint2*)(row + c4)      = H.u;
    *(uint2*)(row + EE + c4) = L.u;
}

// ---------------------------------------------------------------------------
// splitAttn: attn fp32 [16384 x 128] -> fp16 [16384 x 256] = [hi | lo]
// ---------------------------------------------------------------------------
__global__ __launch_bounds__(256) void splitAttn_kernel(const float* __restrict__ src,
                                                        __half* __restrict__ dst) {
    long i = (long)blockIdx.x * 256 + threadIdx.x;   // float4 index (16384*32 total)
    float4 v = ((const float4*)src)[i];
    long r  = i >> 5;
    int  c4 = (int)(i & 31) * 4;
    float vv[4] = {v.x, v.y, v.z, v.w};
    union { __half b[4]; uint2 u; } H, L;
    #pragma unroll
    for (int j = 0; j < 4; j++) {
        __half h = __float2half(vv[j]);
        H.b[j] = h;
        L.b[j] = __float2half(vv[j] - __half2float(h));
    }
    __half* row = dst + r * KAV;
    *(uint2*)(row + c4)      = H.u;
    *(uint2*)(row + SS + c4) = L.u;
}

// ---------------------------------------------------------------------------
// splitB: W fp32 [K=1024][N=1024] -> Bt fp16 [N][2048] = [hi | hi] transposed
// ---------------------------------------------------------------------------
__global__ __launch_bounds__(256) void splitB_kernel(const float* __restrict__ W,
                                                     __half* __restrict__ Bt) {
    __shared__ float tile[32][33];
    int k0 = blockIdx.y * 32, n0 = blockIdx.x * 32;
    int tx = threadIdx.x & 31, ty = threadIdx.x >> 5;  // 32 x 8
    #pragma unroll
    for (int j = 0; j < 32; j += 8)
        tile[ty + j][tx] = W[(long)(k0 + ty + j) * EE + n0 + tx];
    __syncthreads();
    #pragma unroll
    for (int j = 0; j < 32; j += 8) {
        int n = n0 + ty + j, k = k0 + tx;
        __half h = __float2half(tile[tx][ty + j]);
        __half* row = Bt + (long)n * KSPLIT;
        row[k]      = h;
        row[EE + k] = h;
    }
}

// ---------------------------------------------------------------------------
// splitVt: V fp32 [b*128+t][e] -> Vts fp16 [b][e][256] = [hi(t) | hi(t)]
// ---------------------------------------------------------------------------
__global__ __launch_bounds__(256) void splitVt_kernel(const float* __restrict__ V,
                                                      __half* __restrict__ Vts) {
    __shared__ float tile[32][33];
    int b  = blockIdx.z;
    int t0 = blockIdx.y * 32, e0 = blockIdx.x * 32;
    int tx = threadIdx.x & 31, ty = threadIdx.x >> 5;  // 32 x 8
    #pragma unroll
    for (int j = 0; j < 32; j += 8)
        tile[ty + j][tx] = V[((long)b * SS + t0 + ty + j) * EE + e0 + tx];  // tile[t][e]
    __syncthreads();
    #pragma unroll
    for (int j = 0; j < 32; j += 8) {
        int e = e0 + ty + j, t = t0 + tx;
        __half h = __float2half(tile[tx][ty + j]);
        __half* row = Vts + ((long)b * EE + e) * KAV;
        row[t]      = h;
        row[SS + t] = h;
    }
}

// ---------------------------------------------------------------------------
// wmma (HMMA) fp16 GEMM: C[.,1024] = A'[M,LDA] x B'[1024,LDA]^T (+bias), z-batched.
// BM=BN=128, BK=32, 256 threads (8 warps, 4x2), warp tile 32x64 (2x4 frags),
// double-buffered cp.async.  LDA/NCH compile-time (template) for addressing.
// ---------------------------------------------------------------------------
#define WG_LDS   40                  // smem row stride (fp16 elems), 80 bytes
#define WG_BUF   (128 * WG_LDS * 2)  // 10240 bytes per tile

template<int LDA, int NCH>
__global__ __launch_bounds__(256) void wgemm_kernel(
    const __half* __restrict__ A, const __half* __restrict__ B,
    const float* __restrict__ bias, float* __restrict__ C,
    long sA, long sB, long sC) {
    __shared__ __align__(16) char smem_raw[4 * WG_BUF];  // A0,B0,A1,B1 = 40960 B
    uint32_t sbase = smem_u32(smem_raw);

    int tid  = threadIdx.x;
    int wid  = tid >> 5, lane = tid & 31;
    int wm   = wid & 3;         // warp row: rows [wm*32, wm*32+32)
    int wn   = wid >> 2;        // warp col: cols [wn*64, wn*64+64)

    long bz = blockIdx.z;
    const __half* Ab = A + bz * sA;
    const __half* Bb = B + bz * sB;
    float* Cb = C + bz * sC;

    long m0 = (long)blockIdx.y * 128;
    int  n0 = blockIdx.x * 128;

    // cp.async mapping: tile 128x32 fp16 = 512 x 16B segs; 2 per thread per matrix.
    uint32_t dstO[2];
    const char* srcA[2];
    const char* srcB[2];
    #pragma unroll
    for (int u = 0; u < 2; u++) {
        int idx = tid + 256 * u;
        int row = idx >> 2, seg = idx & 3;
        dstO[u] = (uint32_t)row * (WG_LDS * 2) + seg * 16;
        srcA[u] = (const char*)(Ab + (m0 + row) * (long)LDA) + seg * 16;
        srcB[u] = (const char*)(Bb + (long)(n0 + row) * LDA) + seg * 16;
    }

    wmma::fragment<wmma::accumulator, 16, 16, 16, float> acc[2][4];
    #pragma unroll
    for (int i = 0; i < 2; i++)
        #pragma unroll
        for (int j = 0; j < 4; j++) wmma::fill_fragment(acc[i][j], 0.f);

    // prologue: chunk 0 -> buf 0
    #pragma unroll
    for (int u = 0; u < 2; u++) {
        cp16(sbase + dstO[u], srcA[u]);
        cp16(sbase + WG_BUF + dstO[u], srcB[u]);
    }
    CP_COMMIT();

    #pragma unroll 1
    for (int ch = 0; ch < NCH; ch++) {
        if (ch + 1 < NCH) {
            uint32_t off = ((ch + 1) & 1) ? 2u * WG_BUF : 0u;
            long gofs = (long)(ch + 1) * 64;   // 32 fp16 = 64 bytes per chunk
            #pragma unroll
            for (int u = 0; u < 2; u++) {
                cp16(sbase + off + dstO[u], srcA[u] + gofs);
                cp16(sbase + off + WG_BUF + dstO[u], srcB[u] + gofs);
            }
            CP_COMMIT();
            CP_WAIT1();
        } else {
            CP_WAIT0();
        }
        __syncthreads();

        const __half* bufA =
            (const __half*)(smem_raw + ((ch & 1) ? 2 * WG_BUF : 0));
        const __half* bufB = bufA + 128 * WG_LDS;

        #pragma unroll
        for (int kk = 0; kk < 32; kk += 16) {
            wmma::fragment<wmma::matrix_a, 16, 16, 16, __half, wmma::row_major> af[2];
            wmma::fragment<wmma::matrix_b, 16, 16, 16, __half, wmma::col_major> bf[4];
            #pragma unroll
            for (int i = 0; i < 2; i++)
                wmma::load_matrix_sync(af[i], bufA + (wm * 32 + i * 16) * WG_LDS + kk, WG_LDS);
            #pragma unroll
            for (int j = 0; j < 4; j++)
                wmma::load_matrix_sync(bf[j], bufB + (wn * 64 + j * 16) * WG_LDS + kk, WG_LDS);
            #pragma unroll
            for (int i = 0; i < 2; i++)
                #pragma unroll
                for (int j = 0; j < 4; j++)
                    wmma::mma_sync(acc[i][j], af[i], bf[j], acc[i][j]);
        }
        __syncthreads();
    }

    // Epilogue: per-warp SMEM staging (16x68 f32) -> coalesced STG (+bias)
    float* stag = (float*)smem_raw + wid * (16 * 68);   // 8 warps x 4352B = 34816
    int erow = lane >> 1, ecb = (lane & 1) * 32;
    #pragma unroll
    for (int mi = 0; mi < 2; mi++) {
        #pragma unroll
        for (int j = 0; j < 4; j++)
            wmma::store_matrix_sync(stag + j * 16, acc[mi][j], 68, wmma::mem_row_major);
        __syncwarp();
        long grow = m0 + wm * 32 + mi * 16 + erow;
        int  gcol = n0 + wn * 64 + ecb;
        #pragma unroll
        for (int f = 0; f < 8; f++) {
            float4 v = *(float4*)(stag + erow * 68 + ecb + f * 4);
            if (bias) {
                float4 b4 = *(const float4*)(bias + gcol + f * 4);
                v.x += b4.x; v.y += b4.y; v.z += b4.z; v.w += b4.w;
            }
            *(float4*)(Cb + grow * EE + gcol + f * 4) = v;
        }
        __syncwarp();
    }
}

// ---------------------------------------------------------------------------
// qin = X @ Wi + bi    (16384x8, K=1024) : one warp per row
// ---------------------------------------------------------------------------
__global__ __launch_bounds__(256) void qin_kernel(const float* __restrict__ X,
                                                  const float* __restrict__ Wi,
                                                  const float* __restrict__ bi) {
    __shared__ float sWi[NQ * EE];
    int tid = threadIdx.x;
    for (int idx = tid; idx < EE * NQ; idx += 256) {
        int k = idx >> 3, o = idx & 7;
        sWi[o * EE + k] = Wi[idx];
    }
    __syncthreads();

    int w = tid >> 5, lane = tid & 31;
    long row = (long)blockIdx.x * 8 + w;
    const float* xr = X + row * EE;

    float acc[NQ];
    #pragma unroll
    for (int o = 0; o < NQ; o++) acc[o] = 0.f;
    for (int k = lane; k < EE; k += 32) {
        float x = xr[k];
        #pragma unroll
        for (int o = 0; o < NQ; o++) acc[o] += x * sWi[o * EE + k];
    }
    float out = 0.f;
    #pragma unroll
    for (int o = 0; o < NQ; o++) {
        float v = acc[o];
        #pragma unroll
        for (int d = 16; d > 0; d >>= 1) v += __shfl_xor_sync(FULLM, v, d);
        if (lane == o) out = v + bi[o];
    }
    if (lane < NQ) d_qin[row * NQ + lane] = out;
}

// ---------------------------------------------------------------------------
// Quantum state sim: one warp per row, state (256 complex) in shared
// ---------------------------------------------------------------------------
__global__ __launch_bounds__(256) void psi_kernel() {
    __shared__ float2 st[8][DIMQ];
    __shared__ float2 gm[NL * NQ * 4];
    __shared__ int    pm[DIMQ];

    int tid = threadIdx.x;
    if (tid < NL * NQ * 4) gm[tid] = d_gates[tid];
    pm[tid] = d_perm[tid];
    __syncthreads();

    int w = tid >> 5, lane = tid & 31;
    long row = (long)blockIdx.x * 8 + w;

    float x = (lane < NQ) ? d_qin[row * NQ + lane] : 0.f;
    float ss, cc;
    sincosf(0.5f * x, &ss, &cc);
    float cq[NQ], sq[NQ];
    #pragma unroll
    for (int q = 0; q < NQ; q++) {
        cq[q] = __shfl_sync(FULLM, cc, q);
        sq[q] = __shfl_sync(FULLM, ss, q);
    }
    #pragma unroll
    for (int j = 0; j < 8; j++) {
        int i = lane + 32 * j;
        float a = 1.f;
        #pragma unroll
        for (int q = 0; q < NQ; q++)
            a *= ((i >> (NQ - 1 - q)) & 1) ? sq[q] : cq[q];
        st[w][i] = make_float2(a, 0.f);
    }
    __syncwarp();

    for (int l = 0; l < NL; l++) {
        #pragma unroll
        for (int q = 0; q < NQ; q++) {
            const float2 m00 = gm[(l * NQ + q) * 4 + 0];
            const float2 m01 = gm[(l * NQ + q) * 4 + 1];
            const float2 m10 = gm[(l * NQ + q) * 4 + 2];
            const float2 m11 = gm[(l * NQ + q) * 4 + 3];
            int stride = 1 << (NQ - 1 - q);
            #pragma unroll
            for (int pp = 0; pp < 4; pp++) {
                int p  = lane + 32 * pp;
                int i0 = ((p & ~(stride - 1)) << 1) | (p & (stride - 1));
                int i1 = i0 | stride;
                float2 a0 = st[w][i0];
                float2 a1 = st[w][i1];
                float2 n0, n1;
                n0.x = m00.x * a0.x - m00.y * a0.y + m01.x * a1.x - m01.y * a1.y;
                n0.y = m00.x * a0.y + m00.y * a0.x + m01.x * a1.y + m01.y * a1.x;
                n1.x = m10.x * a0.x - m10.y * a0.y + m11.x * a1.x - m11.y * a1.y;
                n1.y = m10.x * a0.y + m10.y * a0.x + m11.x * a1.y + m11.y * a1.x;
                st[w][i0] = n0;
                st[w][i1] = n1;
            }
            __syncwarp();
        }
        float2 tmp[8];
        #pragma unroll
        for (int j = 0; j < 8; j++) tmp[j] = st[w][pm[lane + 32 * j]];
        __syncwarp();
        #pragma unroll
        for (int j = 0; j < 8; j++) st[w][lane + 32 * j] = tmp[j];
        __syncwarp();
    }
    #pragma unroll
    for (int j = 0; j < 8; j++)
        d_psi[row * DIMQ + lane + 32 * j] = st[w][lane + 32 * j];
}

// ---------------------------------------------------------------------------
// Gram + kernel-matrix + softmax -> attn.  TWO blocks per batch (64 s-rows
// each), 512 threads: 16 row-groups x 4 rows, 32 t-lanes x 4.
// ---------------------------------------------------------------------------
__global__ __launch_bounds__(512) void gram_kernel(const float* __restrict__ phi,
                                                   float* __restrict__ attn) {
    const int DC = 16;
    __shared__ float2 P[SS][DC + 1];

    int b   = blockIdx.x;
    int sh  = blockIdx.y;      // 0/1 -> s-rows [sh*64, sh*64+64)
    int tid = threadIdx.x;
    int ts  = tid >> 5;
    int tt  = tid & 31;

    float accr[4][4], acci[4][4];
    #pragma unroll
    for (int j = 0; j < 4; j++)
        #pragma unroll
        for (int k = 0; k < 4; k++) { accr[j][k] = 0.f; acci[j][k] = 0.f; }

    const float2* pb = d_psi + (long)b * SS * DIMQ;

    for (int d0 = 0; d0 < DIMQ; d0 += DC) {
        #pragma unroll
        for (int u = 0; u < 4; u++) {
            int idx = tid + 512 * u;
            int r = idx >> 4, dd = idx & 15;
            P[r][dd] = pb[(long)r * DIMQ + d0 + dd];
        }
        __syncthreads();
        #pragma unroll 4
        for (int dd = 0; dd < DC; dd++) {
            float2 sf[4], tf[4];
            #pragma unroll
            for (int j = 0; j < 4; j++) sf[j] = P[sh * 64 + ts * 4 + j][dd];
            #pragma unroll
            for (int k = 0; k < 4; k++) tf[k] = P[tt + 32 * k][dd];
            #pragma unroll
            for (int j = 0; j < 4; j++)
                #pragma unroll
                for (int k = 0; k < 4; k++) {
                    accr[j][k] += sf[j].x * tf[k].x + sf[j].y * tf[k].y;
                    acci[j][k] += sf[j].y * tf[k].x - sf[j].x * tf[k].y;
                }
        }
        __syncthreads();
    }

    const float inv = 0.3535533905932738f;
    float pht[4];
    #pragma unroll
    for (int k = 0; k < 4; k++) pht[k] = phi[tt + 32 * k];

    #pragma unroll
    for (int j = 0; j < 4; j++) {
        int srow = sh * 64 + ts * 4 + j;
        float ph_s = phi[srow];
        float kv[4];
        float mx = -1e30f;
        #pragma unroll
        for (int k = 0; k < 4; k++) {
            float g2 = accr[j][k] * accr[j][k] + acci[j][k] * acci[j][k];
            kv[k] = g2 * inv + cosf(pht[k] - ph_s);
            mx = fmaxf(mx, kv[k]);
        }
        #pragma unroll
        for (int d = 16; d > 0; d >>= 1) mx = fmaxf(mx, __shfl_xor_sync(FULLM, mx, d));
        float sum = 0.f;
        #pragma unroll
        for (int k = 0; k < 4; k++) { kv[k] = expf(kv[k] - mx); sum += kv[k]; }
        #pragma unroll
        for (int d = 16; d > 0; d >>= 1) sum += __shfl_xor_sync(FULLM, sum, d);
        float is = 1.f / sum;
        #pragma unroll
        for (int k = 0; k < 4; k++)
            attn[(long)b * SS * SS + (long)srow * SS + tt + 32 * k] = kv[k] * is;
    }
}

// ---------------------------------------------------------------------------
extern "C" void kernel_launch(void* const* d_in, const int* in_sizes, int n_in,
                              void* d_out, int out_size) {
    const float* X     = (const float*)d_in[0];
    const float* Wi    = (const float*)d_in[1];
    const float* bi    = (const float*)d_in[2];
    const float* Wv    = (const float*)d_in[3];
    const float* bv    = (const float*)d_in[4];
    const float* Wo    = (const float*)d_in[5];
    const float* bo    = (const float*)d_in[6];
    const float* theta = (const float*)d_in[7];
    const float* phi   = (const float*)d_in[8];

    float* y    = (float*)d_out;
    float* attn = (float*)d_out + Y_SIZE;

    float *pV, *pT;
    __half *pXs, *pTs, *pWvs, *pWos, *pAs, *pVts;
    cudaGetSymbolAddress((void**)&pV, d_V);
    cudaGetSymbolAddress((void**)&pT, d_T);
    cudaGetSymbolAddress((void**)&pXs, d_Xs);
    cudaGetSymbolAddress((void**)&pTs, d_Ts);
    cudaGetSymbolAddress((void**)&pWvs, d_Wvs);
    cudaGetSymbolAddress((void**)&pWos, d_Wos);
    cudaGetSymbolAddress((void**)&pAs, d_attns);
    cudaGetSymbolAddress((void**)&pVts, d_Vts);

    // prep + splits
    prep_kernel<<<1, 256>>>(theta);
    {
        dim3 g(EE / 32, EE / 32);
        splitB_kernel<<<g, 256>>>(Wv, pWvs);
        splitB_kernel<<<g, 256>>>(Wo, pWos);
    }
    splitA_kernel<<<ROWS, 256>>>(X, pXs);
    qin_kernel<<<ROWS / 8, 256>>>(X, Wi, bi);

    // V = X@Wv + bv  (wmma fp16 2-term)
    {
        dim3 grid(EE / 128, ROWS / 128, 1);
        wgemm_kernel<KSPLIT, KSPLIT / 32><<<grid, 256>>>(pXs, pWvs, bv, pV, 0, 0, 0);
    }

    // quantum states + Gram/softmax
    psi_kernel<<<ROWS / 8, 256>>>();
    gram_kernel<<<dim3(NB, 2), 512>>>(phi, attn);

    // splits for attn@V
    {
        dim3 g(EE / 32, SS / 32, NB);
        splitVt_kernel<<<g, 256>>>(pV, pVts);
    }
    splitAttn_kernel<<<ROWS * 32 / 256, 256>>>(attn, pAs);

    // T = attn @ V (wmma, batched over z)
    {
        dim3 grid(EE / 128, 1, NB);
        wgemm_kernel<KAV, KAV / 32><<<grid, 256>>>(pAs, pVts, nullptr, pT,
                                                   (long)SS * KAV, (long)EE * KAV,
                                                   (long)SS * EE);
    }

    // split T, then y = T@Wo + bo (wmma fp16 2-term)
    splitA_kernel<<<ROWS, 256>>>(pT, pTs);
    {
        dim3 grid(EE / 128, ROWS / 128, 1);
        wgemm_kernel<KSPLIT, KSPLIT / 32><<<grid, 256>>>(pTs, pWos, bo, y, 0, 0, 0);
    }
}

// round 12
// speedup vs baseline: 1.4329x; 1.0149x over previous
#include <cuda_runtime.h>
#include <cuda_fp16.h>
#include <mma.h>
#include <math.h>
#include <stdint.h>

using namespace nvcuda;

// Problem constants (fixed shapes)
#define NB      128          // batch
#define SS      128          // seq
#define EE      1024         // embed
#define NQ      8            // qubits
#define NL      4            // layers
#define DIMQ    256          // 2^NQ
#define ROWS    16384        // NB*SS
#define KSPLIT  2048         // 2*EE  (fp16 2-term split: A=[hi|lo], B=[hi|hi])
#define KAV     256          // 2*SS  (attn@V split K)
#define Y_SIZE  16777216L    // NB*SS*EE

// Scratch (static device globals — allowed)
__device__ float  d_qin[ROWS * NQ];
__device__ float2 d_gates[NL * NQ * 4];
__device__ int    d_perm[DIMQ];
__device__ float2 d_psi[(long)ROWS * DIMQ];
__device__ float  d_V[(long)ROWS * EE];
__device__ __half d_Xs[(long)ROWS * KSPLIT];    // split X    [M][2K]
__device__ __half d_Ts[(long)ROWS * KSPLIT];    // split T    [M][2K]  (written by attn@V wgemm)
__device__ __half d_Wvs[(long)EE * KSPLIT];     // Wv^T       [N][2K] = [hi|hi]
__device__ __half d_Wos[(long)EE * KSPLIT];     // Wo^T       [N][2K] = [hi|hi]
__device__ __half d_attns[(long)ROWS * KAV];    // split attn [b*s][2*128] (written by gram)
__device__ __half d_Vts[(long)NB * EE * KAV];   // V^T        [b][e][2*128] = [hi|hi]

#define FULLM 0xffffffffu

// ---------------------------------------------------------------------------
// cp.async helpers (sm_80+ baseline — no 'a'-suffix features!)
// ---------------------------------------------------------------------------
__device__ __forceinline__ uint32_t smem_u32(const void* p) {
    uint32_t a;
    asm("{ .reg .u64 t; cvta.to.shared.u64 t, %1; cvt.u32.u64 %0, t; }" : "=r"(a) : "l"(p));
    return a;
}
__device__ __forceinline__ void cp16(uint32_t s, const void* g) {
    asm volatile("cp.async.cg.shared.global [%0], [%1], 16;" :: "r"(s), "l"(g));
}
#define CP_COMMIT() asm volatile("cp.async.commit_group;" ::: "memory")
#define CP_WAIT2()  asm volatile("cp.async.wait_group 2;" ::: "memory")
#define CP_WAIT1()  asm volatile("cp.async.wait_group 1;" ::: "memory")
#define CP_WAIT0()  asm volatile("cp.async.wait_group 0;" ::: "memory")

// ---------------------------------------------------------------------------
// Prep: fused RZ*RY gate matrices, composed CNOT-ring perm
// ---------------------------------------------------------------------------
__global__ void prep_kernel(const float* __restrict__ theta) {
    int t = threadIdx.x;
    if (t < NL * NQ) {
        float ty = theta[t * 2 + 0];
        float tz = theta[t * 2 + 1];
        float s, c, zs, zc;
        sincosf(0.5f * ty, &s, &c);
        sincosf(0.5f * tz, &zs, &zc);
        d_gates[t * 4 + 0] = make_float2( c * zc, -c * zs);
        d_gates[t * 4 + 1] = make_float2(-s * zc,  s * zs);
        d_gates[t * 4 + 2] = make_float2( s * zc,  s * zs);
        d_gates[t * 4 + 3] = make_float2( c * zc,  c * zs);
    }
    if (t < DIMQ) {
        int j = t;
        #pragma unroll
        for (int q = NQ - 1; q >= 0; q--) {
            int tq   = (q + 1) & (NQ - 1);
            int cpos = NQ - 1 - q;
            int tpos = NQ - 1 - tq;
            if ((j >> cpos) & 1) j ^= (1 << tpos);
        }
        d_perm[t] = j;
    }
}

// ---------------------------------------------------------------------------
// splitA: fp32 [R x 1024] -> fp16 [R x 2048] laid out [hi | lo]
// ---------------------------------------------------------------------------
__global__ __launch_bounds__(256) void splitA_kernel(const float* __restrict__ src,
                                                     __half* __restrict__ dst) {
    long i = (long)blockIdx.x * 256 + threadIdx.x;   // float4 index
    float4 v = ((const float4*)src)[i];
    long r  = i >> 8;
    int  c4 = (int)(i & 255) * 4;
    float vv[4] = {v.x, v.y, v.z, v.w};
    union { __half b[4]; uint2 u; } H, L;
    #pragma unroll
    for (int j = 0; j < 4; j++) {
        __half h = __float2half(vv[j]);
        H.b[j] = h;
        L.b[j] = __float2half(vv[j] - __half2float(h));
    }
    __half* row = dst + r * KSPLIT;
    *(uint2*)(row + c4)      = H.u;
    *(uint2*)(row + EE + c4) = L.u;
}

// ---------------------------------------------------------------------------
// splitB: W fp32 [K=1024][N=1024] -> Bt fp16 [N][2048] = [hi | hi] transposed
// ---------------------------------------------------------------------------
__global__ __launch_bounds__(256) void splitB_kernel(const float* __restrict__ W,
                                                     __half* __restrict__ Bt) {
    __shared__ float tile[32][33];
    int k0 = blockIdx.y * 32, n0 = blockIdx.x * 32;
    int tx = threadIdx.x & 31, ty = threadIdx.x >> 5;  // 32 x 8
    #pragma unroll
    for (int j = 0; j < 32; j += 8)
        tile[ty + j][tx] = W[(long)(k0 + ty + j) * EE + n0 + tx];
    __syncthreads();
    #pragma unroll
    for (int j = 0; j < 32; j += 8) {
        int n = n0 + ty + j, k = k0 + tx;
        __half h = __float2half(tile[tx][ty + j]);
        __half* row = Bt + (long)n * KSPLIT;
        row[k]      = h;
        row[EE + k] = h;
    }
}

// ---------------------------------------------------------------------------
// splitVt: V fp32 [b*128+t][e] -> Vts fp16 [b][e][256] = [hi(t) | hi(t)]
// ---------------------------------------------------------------------------
__global__ __launch_bounds__(256) void splitVt_kernel(const float* __restrict__ V,
                                                      __half* __restrict__ Vts) {
    __shared__ float tile[32][33];
    int b  = blockIdx.z;
    int t0 = blockIdx.y * 32, e0 = blockIdx.x * 32;
    int tx = threadIdx.x & 31, ty = threadIdx.x >> 5;  // 32 x 8
    #pragma unroll
    for (int j = 0; j < 32; j += 8)
        tile[ty + j][tx] = V[((long)b * SS + t0 + ty + j) * EE + e0 + tx];  // tile[t][e]
    __syncthreads();
    #pragma unroll
    for (int j = 0; j < 32; j += 8) {
        int e = e0 + ty + j, t = t0 + tx;
        __half h = __float2half(tile[tx][ty + j]);
        __half* row = Vts + ((long)b * EE + e) * KAV;
        row[t]      = h;
        row[SS + t] = h;
    }
}

// ---------------------------------------------------------------------------
// wmma (HMMA) fp16 GEMM: C = A'[M,LDA] x B'[1024,LDA]^T, z-batched.
// BM=BN=128, BK=32, 256 threads (8 warps, 4x2), warp tile 32x64 (2x4 frags),
// THREE-stage cp.async pipeline (60KB dynamic smem).
// Stage layout (bytes): [A tile 10240 | B tile 10240] per stage.
// MODE 0: fp32 C (stride EE) + bias.   MODE 1: fp16 [hi|lo] out (stride KSPLIT).
// ---------------------------------------------------------------------------
#define WG_LDS    40                  // smem row stride (fp16 elems), 80 bytes
#define WG_HALF   (128 * WG_LDS)      // 5120 elems = 10240 bytes per matrix
#define WG_STAGE  (2 * WG_HALF * 2)   // A+B per stage = 20480 bytes
#define WG_NSTG   3
#define WG_SMEM   (WG_NSTG * WG_STAGE)  // 61440 bytes

template<int LDA, int NCH, int MODE>
__global__ __launch_bounds__(256) void wgemm_kernel(
    const __half* __restrict__ A, const __half* __restrict__ B,
    const float* __restrict__ bias, float* __restrict__ C,
    __half* __restrict__ aux, long sA, long sB, long sC) {
    extern __shared__ __align__(16) char smem_raw[];
    uint32_t sbase = smem_u32(smem_raw);

    int tid  = threadIdx.x;
    int wid  = tid >> 5, lane = tid & 31;
    int wm   = wid & 3;         // warp row: rows [wm*32, wm*32+32)
    int wn   = wid >> 2;        // warp col: cols [wn*64, wn*64+64)

    long bz = blockIdx.z;
    const __half* Ab = A + bz * sA;
    const __half* Bb = B + bz * sB;

    long m0 = (long)blockIdx.y * 128;
    int  n0 = blockIdx.x * 128;

    // cp.async mapping: tile 128x32 fp16 = 512 x 16B segs; 2 per thread per matrix.
    uint32_t dstO[2];
    const char* srcA[2];
    const char* srcB[2];
    #pragma unroll
    for (int u = 0; u < 2; u++) {
        int idx = tid + 256 * u;
        int row = idx >> 2, seg = idx & 3;
        dstO[u] = (uint32_t)row * (WG_LDS * 2) + seg * 16;
        srcA[u] = (const char*)(Ab + (m0 + row) * (long)LDA) + seg * 16;
        srcB[u] = (const char*)(Bb + (long)(n0 + row) * LDA) + seg * 16;
    }

    wmma::fragment<wmma::accumulator, 16, 16, 16, float> acc[2][4];
    #pragma unroll
    for (int i = 0; i < 2; i++)
        #pragma unroll
        for (int j = 0; j < 4; j++) wmma::fill_fragment(acc[i][j], 0.f);

    // prologue: chunks 0,1 -> stages 0,1   (B at byte offset 2*WG_HALF = 10240)
    #pragma unroll
    for (int p = 0; p < 2; p++) {
        uint32_t st = sbase + p * WG_STAGE;
        long gofs = (long)p * 64;
        #pragma unroll
        for (int u = 0; u < 2; u++) {
            cp16(st + dstO[u], srcA[u] + gofs);
            cp16(st + 2 * WG_HALF + dstO[u], srcB[u] + gofs);
        }
        CP_COMMIT();
    }

    int stage = 0;      // stage holding chunk ch
    int nstage = 2;     // stage to fill with chunk ch+2
    #pragma unroll 1
    for (int ch = 0; ch < NCH; ch++) {
        if (ch + 2 < NCH) {
            uint32_t st = sbase + nstage * WG_STAGE;
            long gofs = (long)(ch + 2) * 64;
            #pragma unroll
            for (int u = 0; u < 2; u++) {
                cp16(st + dstO[u], srcA[u] + gofs);
                cp16(st + 2 * WG_HALF + dstO[u], srcB[u] + gofs);
            }
            CP_COMMIT();
            CP_WAIT2();
        } else if (ch + 1 < NCH) {
            CP_WAIT1();
        } else {
            CP_WAIT0();
        }
        __syncthreads();

        const __half* bufA = (const __half*)(smem_raw + stage * WG_STAGE);
        const __half* bufB = bufA + WG_HALF;   // +5120 elems = +10240 BYTES (matches store)

        #pragma unroll
        for (int kk = 0; kk < 32; kk += 16) {
            wmma::fragment<wmma::matrix_a, 16, 16, 16, __half, wmma::row_major> af[2];
            wmma::fragment<wmma::matrix_b, 16, 16, 16, __half, wmma::col_major> bf[4];
            #pragma unroll
            for (int i = 0; i < 2; i++)
                wmma::load_matrix_sync(af[i], bufA + (wm * 32 + i * 16) * WG_LDS + kk, WG_LDS);
            #pragma unroll
            for (int j = 0; j < 4; j++)
                wmma::load_matrix_sync(bf[j], bufB + (wn * 64 + j * 16) * WG_LDS + kk, WG_LDS);
            #pragma unroll
            for (int i = 0; i < 2; i++)
                #pragma unroll
                for (int j = 0; j < 4; j++)
                    wmma::mma_sync(acc[i][j], af[i], bf[j], acc[i][j]);
        }
        __syncthreads();
        stage  = (stage == WG_NSTG - 1) ? 0 : stage + 1;
        nstage = (nstage == WG_NSTG - 1) ? 0 : nstage + 1;
    }

    // Epilogue: per-warp SMEM staging (16x68 f32) -> coalesced stores
    float* stag = (float*)smem_raw + wid * (16 * 68);   // 8 warps x 4352B = 34816
    int erow = lane >> 1, ecb = (lane & 1) * 32;
    float* Cb = (MODE == 0) ? (C + bz * sC) : nullptr;
    __half* Ab2 = (MODE == 1) ? (aux + bz * sC) : nullptr;
    #pragma unroll
    for (int mi = 0; mi < 2; mi++) {
        #pragma unroll
        for (int j = 0; j < 4; j++)
            wmma::store_matrix_sync(stag + j * 16, acc[mi][j], 68, wmma::mem_row_major);
        __syncwarp();
        long grow = m0 + wm * 32 + mi * 16 + erow;
        int  gcol = n0 + wn * 64 + ecb;
        #pragma unroll
        for (int f = 0; f < 8; f++) {
            float4 v = *(float4*)(stag + erow * 68 + ecb + f * 4);
            if (MODE == 0) {
                if (bias) {
                    float4 b4 = *(const float4*)(bias + gcol + f * 4);
                    v.x += b4.x; v.y += b4.y; v.z += b4.z; v.w += b4.w;
                }
                *(float4*)(Cb + grow * EE + gcol + f * 4) = v;
            } else {
                float vv[4] = {v.x, v.y, v.z, v.w};
                union { __half b[4]; uint2 u; } H, L;
                #pragma unroll
                for (int q = 0; q < 4; q++) {
                    __half h = __float2half(vv[q]);
                    H.b[q] = h;
                    L.b[q] = __float2half(vv[q] - __half2float(h));
                }
                __half* rowp = Ab2 + grow * KSPLIT + gcol + f * 4;
                *(uint2*)(rowp)      = H.u;
                *(uint2*)(rowp + EE) = L.u;
            }
        }
        __syncwarp();
    }
}

// ---------------------------------------------------------------------------
// qin = X @ Wi + bi    (16384x8, K=1024) : one warp per row
// ---------------------------------------------------------------------------
__global__ __launch_bounds__(256) void qin_kernel(const float* __restrict__ X,
                                                  const float* __restrict__ Wi,
                                                  const float* __restrict__ bi) {
    __shared__ float sWi[NQ * EE];
    int tid = threadIdx.x;
    for (int idx = tid; idx < EE * NQ; idx += 256) {
        int k = idx >> 3, o = idx & 7;
        sWi[o * EE + k] = Wi[idx];
    }
    __syncthreads();

    int w = tid >> 5, lane = tid & 31;
    long row = (long)blockIdx.x * 8 + w;
    const float* xr = X + row * EE;

    float acc[NQ];
    #pragma unroll
    for (int o = 0; o < NQ; o++) acc[o] = 0.f;
    for (int k = lane; k < EE; k += 32) {
        float x = xr[k];
        #pragma unroll
        for (int o = 0; o < NQ; o++) acc[o] += x * sWi[o * EE + k];
    }
    float out = 0.f;
    #pragma unroll
    for (int o = 0; o < NQ; o++) {
        float v = acc[o];
        #pragma unroll
        for (int d = 16; d > 0; d >>= 1) v += __shfl_xor_sync(FULLM, v, d);
        if (lane == o) out = v + bi[o];
    }
    if (lane < NQ) d_qin[row * NQ + lane] = out;
}

// ---------------------------------------------------------------------------
// Quantum state sim: one warp per row, state (256 complex) in shared
// ---------------------------------------------------------------------------
__global__ __launch_bounds__(256) void psi_kernel() {
    __shared__ float2 st[8][DIMQ];
    __shared__ float2 gm[NL * NQ * 4];
    __shared__ int    pm[DIMQ];

    int tid = threadIdx.x;
    if (tid < NL * NQ * 4) gm[tid] = d_gates[tid];
    pm[tid] = d_perm[tid];
    __syncthreads();

    int w = tid >> 5, lane = tid & 31;
    long row = (long)blockIdx.x * 8 + w;

    float x = (lane < NQ) ? d_qin[row * NQ + lane] : 0.f;
    float ss, cc;
    sincosf(0.5f * x, &ss, &cc);
    float cq[NQ], sq[NQ];
    #pragma unroll
    for (int q = 0; q < NQ; q++) {
        cq[q] = __shfl_sync(FULLM, cc, q);
        sq[q] = __shfl_sync(FULLM, ss, q);
    }
    #pragma unroll
    for (int j = 0; j < 8; j++) {
        int i = lane + 32 * j;
        float a = 1.f;
        #pragma unroll
        for (int q = 0; q < NQ; q++)
            a *= ((i >> (NQ - 1 - q)) & 1) ? sq[q] : cq[q];
        st[w][i] = make_float2(a, 0.f);
    }
    __syncwarp();

    for (int l = 0; l < NL; l++) {
        #pragma unroll
        for (int q = 0; q < NQ; q++) {
            const float2 m00 = gm[(l * NQ + q) * 4 + 0];
            const float2 m01 = gm[(l * NQ + q) * 4 + 1];
            const float2 m10 = gm[(l * NQ + q) * 4 + 2];
            const float2 m11 = gm[(l * NQ + q) * 4 + 3];
            int stride = 1 << (NQ - 1 - q);
            #pragma unroll
            for (int pp = 0; pp < 4; pp++) {
                int p  = lane + 32 * pp;
                int i0 = ((p & ~(stride - 1)) << 1) | (p & (stride - 1));
                int i1 = i0 | stride;
                float2 a0 = st[w][i0];
                float2 a1 = st[w][i1];
                float2 n0, n1;
                n0.x = m00.x * a0.x - m00.y * a0.y + m01.x * a1.x - m01.y * a1.y;
                n0.y = m00.x * a0.y + m00.y * a0.x + m01.x * a1.y + m01.y * a1.x;
                n1.x = m10.x * a0.x - m10.y * a0.y + m11.x * a1.x - m11.y * a1.y;
                n1.y = m10.x * a0.y + m10.y * a0.x + m11.x * a1.y + m11.y * a1.x;
                st[w][i0] = n0;
                st[w][i1] = n1;
            }
            __syncwarp();
        }
        float2 tmp[8];
        #pragma unroll
        for (int j = 0; j < 8; j++) tmp[j] = st[w][pm[lane + 32 * j]];
        __syncwarp();
        #pragma unroll
        for (int j = 0; j < 8; j++) st[w][lane + 32 * j] = tmp[j];
        __syncwarp();
    }
    #pragma unroll
    for (int j = 0; j < 8; j++)
        d_psi[row * DIMQ + lane + 32 * j] = st[w][lane + 32 * j];
}

// ---------------------------------------------------------------------------
// Gram + kernel-matrix + softmax -> attn (fp32) + fused fp16 [hi|lo] split.
// TWO blocks per batch (64 s-rows each), 512 threads.
// ---------------------------------------------------------------------------
__global__ __launch_bounds__(512) void gram_kernel(const float* __restrict__ phi,
                                                   float* __restrict__ attn,
                                                   __half* __restrict__ attns) {
    const int DC = 16;
    __shared__ float2 P[SS][DC + 1];

    int b   = blockIdx.x;
    int sh  = blockIdx.y;      // 0/1 -> s-rows [sh*64, sh*64+64)
    int tid = threadIdx.x;
    int ts  = tid >> 5;
    int tt  = tid & 31;

    float accr[4][4], acci[4][4];
    #pragma unroll
    for (int j = 0; j < 4; j++)
        #pragma unroll
        for (int k = 0; k < 4; k++) { accr[j][k] = 0.f; acci[j][k] = 0.f; }

    const float2* pb = d_psi + (long)b * SS * DIMQ;

    for (int d0 = 0; d0 < DIMQ; d0 += DC) {
        #pragma unroll
        for (int u = 0; u < 4; u++) {
            int idx = tid + 512 * u;
            int r = idx >> 4, dd = idx & 15;
            P[r][dd] = pb[(long)r * DIMQ + d0 + dd];
        }
        __syncthreads();
        #pragma unroll 4
        for (int dd = 0; dd < DC; dd++) {
            float2 sf[4], tf[4];
            #pragma unroll
            for (int j = 0; j < 4; j++) sf[j] = P[sh * 64 + ts * 4 + j][dd];
            #pragma unroll
            for (int k = 0; k < 4; k++) tf[k] = P[tt + 32 * k][dd];
            #pragma unroll
            for (int j = 0; j < 4; j++)
                #pragma unroll
                for (int k = 0; k < 4; k++) {
                    accr[j][k] += sf[j].x * tf[k].x + sf[j].y * tf[k].y;
                    acci[j][k] += sf[j].y * tf[k].x - sf[j].x * tf[k].y;
                }
        }
        __syncthreads();
    }

    const float inv = 0.3535533905932738f;
    float pht[4];
    #pragma unroll
    for (int k = 0; k < 4; k++) pht[k] = phi[tt + 32 * k];

    #pragma unroll
    for (int j = 0; j < 4; j++) {
        int srow = sh * 64 + ts * 4 + j;
        float ph_s = phi[srow];
        float kv[4];
        float mx = -1e30f;
        #pragma unroll
        for (int k = 0; k < 4; k++) {
            float g2 = accr[j][k] * accr[j][k] + acci[j][k] * acci[j][k];
            kv[k] = g2 * inv + cosf(pht[k] - ph_s);
            mx = fmaxf(mx, kv[k]);
        }
        #pragma unroll
        for (int d = 16; d > 0; d >>= 1) mx = fmaxf(mx, __shfl_xor_sync(FULLM, mx, d));
        float sum = 0.f;
        #pragma unroll
        for (int k = 0; k < 4; k++) { kv[k] = expf(kv[k] - mx); sum += kv[k]; }
        #pragma unroll
        for (int d = 16; d > 0; d >>= 1) sum += __shfl_xor_sync(FULLM, sum, d);
        float is = 1.f / sum;
        long arow = (long)b * SS + srow;
        #pragma unroll
        for (int k = 0; k < 4; k++) {
            float a = kv[k] * is;
            attn[(long)b * SS * SS + (long)srow * SS + tt + 32 * k] = a;
            __half h = __float2half(a);
            __half l = __float2half(a - __half2float(h));
            attns[arow * KAV + tt + 32 * k]      = h;
            attns[arow * KAV + SS + tt + 32 * k] = l;
        }
    }
}

// ---------------------------------------------------------------------------
extern "C" void kernel_launch(void* const* d_in, const int* in_sizes, int n_in,
                              void* d_out, int out_size) {
    const float* X     = (const float*)d_in[0];
    const float* Wi    = (const float*)d_in[1];
    const float* bi    = (const float*)d_in[2];
    const float* Wv    = (const float*)d_in[3];
    const float* bv    = (const float*)d_in[4];
    const float* Wo    = (const float*)d_in[5];
    const float* bo    = (const float*)d_in[6];
    const float* theta = (const float*)d_in[7];
    const float* phi   = (const float*)d_in[8];

    float* y    = (float*)d_out;
    float* attn = (float*)d_out + Y_SIZE;

    float *pV;
    __half *pXs, *pTs, *pWvs, *pWos, *pAs, *pVts;
    cudaGetSymbolAddress((void**)&pV, d_V);
    cudaGetSymbolAddress((void**)&pXs, d_Xs);
    cudaGetSymbolAddress((void**)&pTs, d_Ts);
    cudaGetSymbolAddress((void**)&pWvs, d_Wvs);
    cudaGetSymbolAddress((void**)&pWos, d_Wos);
    cudaGetSymbolAddress((void**)&pAs, d_attns);
    cudaGetSymbolAddress((void**)&pVts, d_Vts);

    // dynamic smem opt-in (host-side attribute config; idempotent)
    cudaFuncSetAttribute((const void*)wgemm_kernel<KSPLIT, KSPLIT / 32, 0>,
                         cudaFuncAttributeMaxDynamicSharedMemorySize, WG_SMEM);
    cudaFuncSetAttribute((const void*)wgemm_kernel<KAV, KAV / 32, 1>,
                         cudaFuncAttributeMaxDynamicSharedMemorySize, WG_SMEM);

    // prep + splits
    prep_kernel<<<1, 256>>>(theta);
    {
        dim3 g(EE / 32, EE / 32);
        splitB_kernel<<<g, 256>>>(Wv, pWvs);
        splitB_kernel<<<g, 256>>>(Wo, pWos);
    }
    splitA_kernel<<<ROWS, 256>>>(X, pXs);
    qin_kernel<<<ROWS / 8, 256>>>(X, Wi, bi);

    // V = X@Wv + bv  (wmma fp16 2-term, 3-stage pipeline)
    {
        dim3 grid(EE / 128, ROWS / 128, 1);
        wgemm_kernel<KSPLIT, KSPLIT / 32, 0><<<grid, 256, WG_SMEM>>>(
            pXs, pWvs, bv, pV, nullptr, 0, 0, 0);
    }

    // quantum states + Gram/softmax (writes fp32 attn + fp16 split)
    psi_kernel<<<ROWS / 8, 256>>>();
    gram_kernel<<<dim3(NB, 2), 512>>>(phi, attn, pAs);

    // V^T split for attn@V
    {
        dim3 g(EE / 32, SS / 32, NB);
        splitVt_kernel<<<g, 256>>>(pV, pVts);
    }

    // T = attn @ V (wmma, batched over z) -> emits Ts = [hi|lo] fp16 directly
    {
        dim3 grid(EE / 128, 1, NB);
        wgemm_kernel<KAV, KAV / 32, 1><<<grid, 256, WG_SMEM>>>(
            pAs, pVts, nullptr, nullptr, pTs,
            (long)SS * KAV, (long)EE * KAV, (long)SS * KSPLIT);
    }

    // y = T @ Wo + bo (wmma fp16 2-term, 3-stage pipeline)
    {
        dim3 grid(EE / 128, ROWS / 128, 1);
        wgemm_kernel<KSPLIT, KSPLIT / 32, 0><<<grid, 256, WG_SMEM>>>(
            pTs, pWos, bo, y, nullptr, 0, 0, 0);
    }
}